// round 2
// baseline (speedup 1.0000x reference)
#include <cuda_runtime.h>
#include <math.h>

// Problem constants
#define MROWS   65536        // B*N = 8*8192
#define FDIM    128
#define KCLUST  512
#define TM      32           // rows per CTA
#define TK      64           // centers per chunk
#define THREADS 256
#define NCHUNK  (KCLUST / TK)

// SMEM pitches (in floats)
#define PX   132             // x tile pitch (4-aligned)
#define PSC  516             // scores pitch (4-aligned)
#define PC2  129             // C chunk pitch for phase 2 (odd -> conflict-free scalar LDS)
#define PC4  132             // C chunk pitch for phase 4 (4-aligned -> float4 LDS)

__device__ float g_csq[KCLUST];

__global__ void csq_kernel(const float* __restrict__ cc) {
    int c = blockIdx.x * blockDim.x + threadIdx.x;
    if (c < KCLUST) {
        const float* p = cc + (size_t)c * FDIM;
        float s = 0.f;
        #pragma unroll 16
        for (int f = 0; f < FDIM; ++f) s = fmaf(p[f], p[f], s);
        g_csq[c] = s;
    }
}

extern __shared__ float smem[];

__global__ __launch_bounds__(THREADS, 1)
void cluster_kernel(const float* __restrict__ x, const float* __restrict__ cc,
                    float* __restrict__ out) {
    float* Xs   = smem;                   // TM*PX
    float* sc   = Xs + TM * PX;           // TM*PSC
    float* Cs   = sc + TM * PSC;          // TK*PC4 (>= TK*PC2)
    float* xsq  = Cs + TK * PC4;          // TM
    float* rinv = xsq + TM;               // TM

    const int tid      = threadIdx.x;
    const int wid      = tid >> 5;
    const int lane     = tid & 31;
    const int row_base = blockIdx.x * TM;

    // ---- load x tile (32 x 128) ----
    #pragma unroll
    for (int j = 0; j < 4; ++j) {
        int g = 4 * (tid + THREADS * j);          // 0..4095
        int r = g >> 7, f = g & 127;
        float4 v = *(const float4*)(x + (size_t)(row_base + r) * FDIM + f);
        *(float4*)(Xs + r * PX + f) = v;
    }
    __syncthreads();

    // ---- xsq per row (8 threads per row) ----
    {
        int r = tid >> 3, part = tid & 7;
        float s = 0.f;
        #pragma unroll
        for (int u = 0; u < 4; ++u) {
            float4 v = *(float4*)(Xs + r * PX + part * 16 + u * 4);
            s += v.x * v.x + v.y * v.y + v.z * v.z + v.w * v.w;
        }
        s += __shfl_xor_sync(0xffffffffu, s, 1);
        s += __shfl_xor_sync(0xffffffffu, s, 2);
        s += __shfl_xor_sync(0xffffffffu, s, 4);
        if (part == 0) xsq[r] = s;
    }

    // ================= phase 2: distances (32 x 512) =================
    const int rg = tid >> 4;          // 0..15
    const int cg = tid & 15;          // 0..15
    const int r0 = 2 * rg, r1 = r0 + 1;

    // prefetch chunk 0 into registers (warp w loads centers 8w..8w+7)
    float pre[8][4];
    #pragma unroll
    for (int c2 = 0; c2 < 8; ++c2)
        #pragma unroll
        for (int u = 0; u < 4; ++u)
            pre[c2][u] = cc[(size_t)(8 * wid + c2) * FDIM + lane + 32 * u];

    for (int kc = 0; kc < NCHUNK; ++kc) {
        __syncthreads();
        #pragma unroll
        for (int c2 = 0; c2 < 8; ++c2)
            #pragma unroll
            for (int u = 0; u < 4; ++u)
                Cs[(8 * wid + c2) * PC2 + lane + 32 * u] = pre[c2][u];
        __syncthreads();
        if (kc + 1 < NCHUNK) {
            #pragma unroll
            for (int c2 = 0; c2 < 8; ++c2)
                #pragma unroll
                for (int u = 0; u < 4; ++u)
                    pre[c2][u] = cc[(size_t)((kc + 1) * TK + 8 * wid + c2) * FDIM + lane + 32 * u];
        }

        float acc0[4] = {0.f, 0.f, 0.f, 0.f};
        float acc1[4] = {0.f, 0.f, 0.f, 0.f};
        #pragma unroll 4
        for (int f = 0; f < FDIM; f += 4) {
            float4 a0 = *(float4*)(Xs + r0 * PX + f);
            float4 a1 = *(float4*)(Xs + r1 * PX + f);
            #pragma unroll
            for (int u = 0; u < 4; ++u) {
                float au0 = (&a0.x)[u], au1 = (&a1.x)[u];
                #pragma unroll
                for (int j = 0; j < 4; ++j) {
                    float b = Cs[(cg + 16 * j) * PC2 + f + u];
                    acc0[j] = fmaf(au0, b, acc0[j]);
                    acc1[j] = fmaf(au1, b, acc1[j]);
                }
            }
        }

        float xs0 = xsq[r0], xs1 = xsq[r1];
        #pragma unroll
        for (int j = 0; j < 4; ++j) {
            int c = kc * TK + cg + 16 * j;
            float cq = g_csq[c];
            float d0 = fmaxf(fmaf(-2.f, acc0[j], xs0 + cq), 0.f);
            float d1 = fmaxf(fmaf(-2.f, acc1[j], xs1 + cq), 0.f);
            sc[r0 * PSC + c] = sqrtf(d0);
            sc[r1 * PSC + c] = sqrtf(d1);
        }
    }
    __syncthreads();

    // ================= phase 3: softmax(-dist) per row =================
    {
        #pragma unroll
        for (int q = 0; q < 4; ++q) {
            int r = wid * 4 + q;
            float v[16];
            float mn = 3.4e38f;
            #pragma unroll
            for (int i = 0; i < 16; ++i) {
                v[i] = sc[r * PSC + lane + 32 * i];
                mn = fminf(mn, v[i]);
            }
            #pragma unroll
            for (int m = 16; m; m >>= 1)
                mn = fminf(mn, __shfl_xor_sync(0xffffffffu, mn, m));
            float s = 0.f;
            #pragma unroll
            for (int i = 0; i < 16; ++i) {
                float p = __expf(mn - v[i]);   // <= 1
                s += p;
                sc[r * PSC + lane + 32 * i] = p;
            }
            #pragma unroll
            for (int m = 16; m; m >>= 1)
                s += __shfl_xor_sync(0xffffffffu, s, m);
            if (lane == 0) rinv[r] = 1.f / s;
        }
    }
    __syncthreads();

    // ================= phase 4: out = P @ C (32 x 128) =================
    const int fg = tid & 15;
    const int f0 = 8 * fg;
    float acc[2][8];
    #pragma unroll
    for (int i = 0; i < 2; ++i)
        #pragma unroll
        for (int j = 0; j < 8; ++j) acc[i][j] = 0.f;

    float4 pv[8];
    #pragma unroll
    for (int j = 0; j < 8; ++j)
        pv[j] = *(const float4*)(cc + 4 * (tid + THREADS * j));

    for (int kc = 0; kc < NCHUNK; ++kc) {
        __syncthreads();
        #pragma unroll
        for (int j = 0; j < 8; ++j) {
            int g = 4 * (tid + THREADS * j);
            int c = g >> 7, f = g & 127;
            *(float4*)(Cs + c * PC4 + f) = pv[j];
        }
        __syncthreads();
        if (kc + 1 < NCHUNK) {
            #pragma unroll
            for (int j = 0; j < 8; ++j)
                pv[j] = *(const float4*)(cc + (size_t)(kc + 1) * TK * FDIM + 4 * (tid + THREADS * j));
        }

        #pragma unroll 4
        for (int k = 0; k < TK; k += 4) {
            int kk = kc * TK + k;
            float4 p0 = *(float4*)(sc + r0 * PSC + kk);
            float4 p1 = *(float4*)(sc + r1 * PSC + kk);
            #pragma unroll
            for (int u = 0; u < 4; ++u) {
                float4 b0 = *(float4*)(Cs + (k + u) * PC4 + f0);
                float4 b1 = *(float4*)(Cs + (k + u) * PC4 + f0 + 4);
                float w0 = (&p0.x)[u], w1 = (&p1.x)[u];
                acc[0][0] = fmaf(w0, b0.x, acc[0][0]);
                acc[0][1] = fmaf(w0, b0.y, acc[0][1]);
                acc[0][2] = fmaf(w0, b0.z, acc[0][2]);
                acc[0][3] = fmaf(w0, b0.w, acc[0][3]);
                acc[0][4] = fmaf(w0, b1.x, acc[0][4]);
                acc[0][5] = fmaf(w0, b1.y, acc[0][5]);
                acc[0][6] = fmaf(w0, b1.z, acc[0][6]);
                acc[0][7] = fmaf(w0, b1.w, acc[0][7]);
                acc[1][0] = fmaf(w1, b0.x, acc[1][0]);
                acc[1][1] = fmaf(w1, b0.y, acc[1][1]);
                acc[1][2] = fmaf(w1, b0.z, acc[1][2]);
                acc[1][3] = fmaf(w1, b0.w, acc[1][3]);
                acc[1][4] = fmaf(w1, b1.x, acc[1][4]);
                acc[1][5] = fmaf(w1, b1.y, acc[1][5]);
                acc[1][6] = fmaf(w1, b1.z, acc[1][6]);
                acc[1][7] = fmaf(w1, b1.w, acc[1][7]);
            }
        }
    }

    // epilogue: scale by 1/sum and store
    float s0 = rinv[r0], s1 = rinv[r1];
    float4 o;
    o.x = acc[0][0] * s0; o.y = acc[0][1] * s0; o.z = acc[0][2] * s0; o.w = acc[0][3] * s0;
    *(float4*)(out + (size_t)(row_base + r0) * FDIM + f0) = o;
    o.x = acc[0][4] * s0; o.y = acc[0][5] * s0; o.z = acc[0][6] * s0; o.w = acc[0][7] * s0;
    *(float4*)(out + (size_t)(row_base + r0) * FDIM + f0 + 4) = o;
    o.x = acc[1][0] * s1; o.y = acc[1][1] * s1; o.z = acc[1][2] * s1; o.w = acc[1][3] * s1;
    *(float4*)(out + (size_t)(row_base + r1) * FDIM + f0) = o;
    o.x = acc[1][4] * s1; o.y = acc[1][5] * s1; o.z = acc[1][6] * s1; o.w = acc[1][7] * s1;
    *(float4*)(out + (size_t)(row_base + r1) * FDIM + f0 + 4) = o;
}

extern "C" void kernel_launch(void* const* d_in, const int* in_sizes, int n_in,
                              void* d_out, int out_size) {
    const float* x  = (const float*)d_in[0];
    const float* cc = (const float*)d_in[1];
    if (n_in >= 2 && in_sizes[0] < in_sizes[1]) {   // robustness: x is the big one
        const float* t = x; x = cc; cc = t;
    }

    size_t smem_bytes = (size_t)(TM * PX + TM * PSC + TK * PC4 + 2 * TM) * sizeof(float);
    cudaFuncSetAttribute(cluster_kernel, cudaFuncAttributeMaxDynamicSharedMemorySize,
                         (int)smem_bytes);

    csq_kernel<<<(KCLUST + 255) / 256, 256>>>(cc);
    cluster_kernel<<<MROWS / TM, THREADS, smem_bytes>>>(x, cc, (float*)d_out);
}

// round 7
// speedup vs baseline: 3.2771x; 3.2771x over previous
#include <cuda_runtime.h>
#include <cstdint>
#include <math.h>

// ---------------- problem constants ----------------
#define MROWS   65536        // B*N
#define FDIM    128
#define KCLUST  512
#define TM      128          // rows per CTA
#define TKC     64           // clusters per chunk
#define NCHUNK  (KCLUST / TKC)   // 8
#define THREADS 256

// ---------------- SMEM layout (float offsets) ----------------
// XF : X tile in m16n8k8 A-fragment order. rows = mt(8)*16 + ks(16), pitch 132
// B1 : C chunk, GEMM1 B-fragment order (n=cluster, k=feat). rows = nt*16+ks, pitch 66
// B2 : C chunk, GEMM2 B-fragment order (n=feat, k=cluster). rows = ks2*16+nt2, pitch 66
// PF : P chunk, GEMM2 A-fragment order. rows = mt(8)*8 + ks2(8), pitch 132
#define XF_OFF   0
#define XF_SZ    (128 * 132)
#define B1H_OFF  (XF_OFF + XF_SZ)
#define B1_SZ    (128 * 66)
#define B1L_OFF  (B1H_OFF + B1_SZ)
#define B2H_OFF  (B1L_OFF + B1_SZ)
#define PF_OFF   (B2H_OFF + B1_SZ)
#define PF_SZ    (64 * 132)
#define CSQ_OFF  (PF_OFF + PF_SZ)
#define XSQ_OFF  (CSQ_OFF + 512)
#define ZS_OFF   (XSQ_OFF + 128)
#define SMEM_FLOATS (ZS_OFF + 128)
#define SMEM_BYTES  (SMEM_FLOATS * 4)

__device__ float g_csq[KCLUST];

__device__ __forceinline__ uint32_t f2tf32(float x) {
    uint32_t h; asm("cvt.rna.tf32.f32 %0, %1;" : "=r"(h) : "f"(x)); return h;
}

// D(16x8) += A(16x8,tf32) * B(8x8,tf32), fp32 accumulate
__device__ __forceinline__ void mma8(float* d, const uint32_t* a, float2 b) {
    asm volatile(
        "mma.sync.aligned.m16n8k8.row.col.f32.tf32.tf32.f32 "
        "{%0,%1,%2,%3}, {%4,%5,%6,%7}, {%8,%9}, {%0,%1,%2,%3};"
        : "+f"(d[0]), "+f"(d[1]), "+f"(d[2]), "+f"(d[3])
        : "r"(a[0]), "r"(a[1]), "r"(a[2]), "r"(a[3]),
          "r"(__float_as_uint(b.x)), "r"(__float_as_uint(b.y)));
}

__global__ void csq_kernel(const float* __restrict__ cc) {
    int c = blockIdx.x * blockDim.x + threadIdx.x;
    if (c < KCLUST) {
        const float* p = cc + (size_t)c * FDIM;
        float s = 0.f;
        #pragma unroll 16
        for (int f = 0; f < FDIM; ++f) s = fmaf(p[f], p[f], s);
        g_csq[c] = s;
    }
}

extern __shared__ float sm[];

__global__ __launch_bounds__(THREADS, 1)
void cluster_mma_kernel(const float* __restrict__ x, const float* __restrict__ cc,
                        float* __restrict__ out) {
    const int tid  = threadIdx.x;
    const int wid  = tid >> 5;
    const int lane = tid & 31;
    const int g    = lane >> 2;     // groupID (row within m16 tile)
    const int tig  = lane & 3;      // thread-in-group
    const int wm   = wid & 3;       // warp m-group: rows [wm*32, wm*32+32)
    const int wn   = wid >> 2;      // warp n-group

    // ---------------- prologue: stage X in A-frag order + row sumsq ----------------
    const float* xbase = x + (size_t)blockIdx.x * TM * FDIM;
    #pragma unroll
    for (int q = 0; q < 16; ++q) {
        int row = q * 8 + wid;
        float4 v = *(const float4*)(xbase + row * FDIM + lane * 4);
        float s = v.x * v.x + v.y * v.y + v.z * v.z + v.w * v.w;
        #pragma unroll
        for (int m = 16; m; m >>= 1) s += __shfl_xor_sync(0xffffffffu, s, m);
        if (lane == 0) sm[XSQ_OFF + row] = s;
        int mt = row >> 4, rm = row & 15;
        int ks = lane >> 1;
        int base = (mt * 16 + ks) * 132 + (rm & 7) * 16 + (rm >> 3) + 2 * (lane & 1);
        #pragma unroll
        for (int j = 0; j < 4; ++j)
            sm[XF_OFF + base + j * 4] = (&v.x)[j];
    }
    sm[CSQ_OFF + tid]       = g_csq[tid];
    sm[CSQ_OFF + 256 + tid] = g_csq[256 + tid];
    if (tid < 128) sm[ZS_OFF + tid] = 0.f;
    __syncthreads();

    float xs[2][2];
    #pragma unroll
    for (int mt = 0; mt < 2; ++mt)
        #pragma unroll
        for (int b = 0; b < 2; ++b)
            xs[mt][b] = sm[XSQ_OFF + wm * 32 + mt * 16 + g + 8 * b];

    float d2acc[2][8][4];
    #pragma unroll
    for (int mt = 0; mt < 2; ++mt)
        #pragma unroll
        for (int nt = 0; nt < 8; ++nt)
            #pragma unroll
            for (int i = 0; i < 4; ++i) d2acc[mt][nt][i] = 0.f;
    float zacc[2][2] = {{0.f, 0.f}, {0.f, 0.f}};

    for (int kc = 0; kc < NCHUNK; ++kc) {
        __syncthreads();   // previous iter's B2/PF consumers done

        // ---- stage C chunk: B1 hi/lo (k=feat) and B2 hi (k=cluster) ----
        const float* cbase = cc + (size_t)kc * TKC * FDIM;
        #pragma unroll
        for (int q = 0; q < 8; ++q) {
            int cl = q * 8 + wid;                      // warp-uniform cluster
            float4 v = *(const float4*)(cbase + cl * FDIM + lane * 4);
            int nt = cl >> 3;
            int ks = lane >> 1;
            int a1base = (nt * 16 + ks) * 66 + (cl & 7) * 8 + (lane & 1);
            int a2base = (nt * 16 + ks) * 66 + (lane & 1) * 32 + (cl & 3) * 2 + ((cl & 7) >> 2);
            #pragma unroll
            for (int j = 0; j < 4; ++j) {
                float val = (&v.x)[j];
                float hi = __uint_as_float(f2tf32(val));
                float lo = val - hi;
                sm[B1H_OFF + a1base + j * 2] = hi;
                sm[B1L_OFF + a1base + j * 2] = lo;
                sm[B2H_OFF + a2base + j * 8] = hi;   // l2 = ((lane&1)*4+j)*4 + (cl&3)
            }
        }
        __syncthreads();

        // ---- GEMM1: S = x . C^T  (3xTF32: hi*hi + hi*lo + lo*hi) ----
        float sacc[2][4][4];
        #pragma unroll
        for (int mt = 0; mt < 2; ++mt)
            #pragma unroll
            for (int nt = 0; nt < 4; ++nt)
                #pragma unroll
                for (int i = 0; i < 4; ++i) sacc[mt][nt][i] = 0.f;

        #pragma unroll
        for (int ks = 0; ks < 16; ++ks) {
            uint32_t ahi[2][4], alo[2][4];
            #pragma unroll
            for (int mt = 0; mt < 2; ++mt) {
                float4 av = *(const float4*)(sm + XF_OFF +
                                ((wm * 2 + mt) * 16 + ks) * 132 + lane * 4);
                #pragma unroll
                for (int j = 0; j < 4; ++j) {
                    float xv = (&av.x)[j];
                    uint32_t h = f2tf32(xv);
                    ahi[mt][j] = h;
                    alo[mt][j] = __float_as_uint(xv - __uint_as_float(h));
                }
            }
            #pragma unroll
            for (int nt = 0; nt < 4; ++nt) {
                int ntg = wn * 4 + nt;
                float2 bh = *(const float2*)(sm + B1H_OFF + (ntg * 16 + ks) * 66 + lane * 2);
                float2 bl = *(const float2*)(sm + B1L_OFF + (ntg * 16 + ks) * 66 + lane * 2);
                #pragma unroll
                for (int mt = 0; mt < 2; ++mt) {
                    mma8(sacc[mt][nt], ahi[mt], bh);
                    mma8(sacc[mt][nt], ahi[mt], bl);
                    mma8(sacc[mt][nt], alo[mt], bh);
                }
            }
        }

        // ---- epilogue: p = exp(-sqrt(xsq+csq-2s)); Z += p; P -> PF ----
        #pragma unroll
        for (int mt = 0; mt < 2; ++mt) {
            #pragma unroll
            for (int nt = 0; nt < 4; ++nt) {
                int ksp = wn * 4 + nt;
                #pragma unroll
                for (int i = 0; i < 4; ++i) {
                    int b   = i >> 1;                 // row-high
                    int clo = 2 * tig + (i & 1);      // cluster within 8-tile
                    int clg = kc * 64 + ksp * 8 + clo;
                    float s   = sacc[mt][nt][i];
                    float d2v = fmaf(-2.f, s, xs[mt][b] + sm[CSQ_OFF + clg]);
                    float d   = sqrtf(fmaxf(d2v, 0.f));
                    float p   = __expf(-d);
                    zacc[mt][b] += p;
                    sm[PF_OFF + ((wm * 2 + mt) * 8 + ksp) * 132 +
                       (g * 4 + (clo & 3)) * 4 + b + 2 * (clo >> 2)] = p;
                }
            }
        }
        __syncthreads();

        // ---- GEMM2: D2 += P . C_chunk ----
        #pragma unroll
        for (int ks2 = 0; ks2 < 8; ++ks2) {
            uint32_t pa[2][4];
            #pragma unroll
            for (int mt = 0; mt < 2; ++mt) {
                float4 pv = *(const float4*)(sm + PF_OFF +
                                ((wm * 2 + mt) * 8 + ks2) * 132 + lane * 4);
                #pragma unroll
                for (int j = 0; j < 4; ++j) pa[mt][j] = f2tf32((&pv.x)[j]);
            }
            #pragma unroll
            for (int nt2 = 0; nt2 < 8; ++nt2) {
                int n2g = wn * 8 + nt2;
                float2 b = *(const float2*)(sm + B2H_OFF + (ks2 * 16 + n2g) * 66 + lane * 2);
                #pragma unroll
                for (int mt = 0; mt < 2; ++mt)
                    mma8(d2acc[mt][nt2], pa[mt], b);
            }
        }
    }

    // ---- Z reduction across tig lanes + the two wn warp-groups ----
    #pragma unroll
    for (int mt = 0; mt < 2; ++mt)
        #pragma unroll
        for (int b = 0; b < 2; ++b) {
            float z = zacc[mt][b];
            z += __shfl_xor_sync(0xffffffffu, z, 1);
            z += __shfl_xor_sync(0xffffffffu, z, 2);
            if (tig == 0)
                atomicAdd(&sm[ZS_OFF + wm * 32 + mt * 16 + g + 8 * b], z);
        }
    __syncthreads();

    // ---- output: out = D2 / Z ----
    float rz[2][2];
    #pragma unroll
    for (int mt = 0; mt < 2; ++mt)
        #pragma unroll
        for (int b = 0; b < 2; ++b)
            rz[mt][b] = 1.f / sm[ZS_OFF + wm * 32 + mt * 16 + g + 8 * b];

    #pragma unroll
    for (int mt = 0; mt < 2; ++mt) {
        #pragma unroll
        for (int nt2 = 0; nt2 < 8; ++nt2) {
            #pragma unroll
            for (int b = 0; b < 2; ++b) {
                size_t rowg = (size_t)blockIdx.x * TM + wm * 32 + mt * 16 + g + 8 * b;
                int f = wn * 64 + nt2 * 8 + 2 * tig;
                float2 o;
                o.x = d2acc[mt][nt2][2 * b]     * rz[mt][b];
                o.y = d2acc[mt][nt2][2 * b + 1] * rz[mt][b];
                *(float2*)(out + rowg * FDIM + f) = o;
            }
        }
    }
}

extern "C" void kernel_launch(void* const* d_in, const int* in_sizes, int n_in,
                              void* d_out, int out_size) {
    const float* x  = (const float*)d_in[0];
    const float* cc = (const float*)d_in[1];
    if (n_in >= 2 && in_sizes[0] < in_sizes[1]) {   // robustness: x is the big one
        const float* t = x; x = cc; cc = t;
    }

    cudaFuncSetAttribute(cluster_mma_kernel, cudaFuncAttributeMaxDynamicSharedMemorySize,
                         SMEM_BYTES);

    csq_kernel<<<(KCLUST + 255) / 256, 256>>>(cc);
    cluster_mma_kernel<<<MROWS / TM, THREADS, SMEM_BYTES>>>(x, cc, (float*)d_out);
}

// round 8
// speedup vs baseline: 3.4180x; 1.0430x over previous
#include <cuda_runtime.h>
#include <cstdint>
#include <math.h>

// ---------------- problem constants ----------------
#define MROWS   65536        // B*N
#define FDIM    128
#define KCLUST  512
#define TM      128          // rows per CTA
#define TKC     64           // clusters per chunk
#define NCHUNK  (KCLUST / TKC)   // 8
#define THREADS 512

// ---------------- SMEM layout (float offsets) ----------------
// XF : X tile in m16n8k8 A-fragment order. rows = mt(8)*16 + ks(16), pitch 132
// B1 : C chunk, GEMM1 B-fragment order (n=cluster, k=feat). rows = nt*16+ks, pitch 66
// B2 : C chunk, GEMM2 B-fragment order (n=feat, k=cluster). rows = ks2*16+nt2, pitch 66
// PF : P chunk, GEMM2 A-fragment order. rows = mt(8)*8 + ks2(8), pitch 132
#define XF_OFF   0
#define XF_SZ    (128 * 132)
#define B1H_OFF  (XF_OFF + XF_SZ)
#define B1_SZ    (128 * 66)
#define B1L_OFF  (B1H_OFF + B1_SZ)
#define B2H_OFF  (B1L_OFF + B1_SZ)
#define PF_OFF   (B2H_OFF + B1_SZ)
#define PF_SZ    (64 * 132)
#define CSQ_OFF  (PF_OFF + PF_SZ)
#define XSQ_OFF  (CSQ_OFF + 512)
#define ZS_OFF   (XSQ_OFF + 128)
#define SMEM_FLOATS (ZS_OFF + 128)
#define SMEM_BYTES  (SMEM_FLOATS * 4)

__device__ float g_csq[KCLUST];

__device__ __forceinline__ uint32_t f2tf32(float x) {
    uint32_t h; asm("cvt.rna.tf32.f32 %0, %1;" : "=r"(h) : "f"(x)); return h;
}

// D(16x8) += A(16x8,tf32) * B(8x8,tf32), fp32 accumulate
__device__ __forceinline__ void mma8(float* d, const uint32_t* a, float2 b) {
    asm volatile(
        "mma.sync.aligned.m16n8k8.row.col.f32.tf32.tf32.f32 "
        "{%0,%1,%2,%3}, {%4,%5,%6,%7}, {%8,%9}, {%0,%1,%2,%3};"
        : "+f"(d[0]), "+f"(d[1]), "+f"(d[2]), "+f"(d[3])
        : "r"(a[0]), "r"(a[1]), "r"(a[2]), "r"(a[3]),
          "r"(__float_as_uint(b.x)), "r"(__float_as_uint(b.y)));
}

__global__ void csq_kernel(const float* __restrict__ cc) {
    int c = blockIdx.x * blockDim.x + threadIdx.x;
    if (c < KCLUST) {
        const float* p = cc + (size_t)c * FDIM;
        float s = 0.f;
        #pragma unroll 16
        for (int f = 0; f < FDIM; ++f) s = fmaf(p[f], p[f], s);
        g_csq[c] = s;
    }
}

extern __shared__ float sm[];

__global__ __launch_bounds__(THREADS, 1)
void cluster_mma_kernel(const float* __restrict__ x, const float* __restrict__ cc,
                        float* __restrict__ out) {
    const int tid  = threadIdx.x;
    const int wid  = tid >> 5;      // 0..15
    const int lane = tid & 31;
    const int g    = lane >> 2;     // groupID (row within m16 tile)
    const int tig  = lane & 3;      // thread-in-group
    const int wm   = wid & 3;       // warp m-group: rows [wm*32, wm*32+32)
    const int wn   = wid >> 2;      // warp n-group: 0..3

    // ---------------- prologue: stage X in A-frag order + row sumsq ----------------
    const float* xbase = x + (size_t)blockIdx.x * TM * FDIM;
    #pragma unroll
    for (int q = 0; q < 8; ++q) {
        int row = q * 16 + wid;
        float4 v = *(const float4*)(xbase + row * FDIM + lane * 4);
        float s = v.x * v.x + v.y * v.y + v.z * v.z + v.w * v.w;
        #pragma unroll
        for (int m = 16; m; m >>= 1) s += __shfl_xor_sync(0xffffffffu, s, m);
        if (lane == 0) sm[XSQ_OFF + row] = s;
        int mt = row >> 4, rm = row & 15;
        int ks = lane >> 1;
        int base = (mt * 16 + ks) * 132 + (rm & 7) * 16 + (rm >> 3) + 2 * (lane & 1);
        #pragma unroll
        for (int j = 0; j < 4; ++j)
            sm[XF_OFF + base + j * 4] = (&v.x)[j];
    }
    if (tid < 512) sm[CSQ_OFF + tid] = g_csq[tid];
    if (tid < 128) sm[ZS_OFF + tid] = 0.f;
    __syncthreads();

    float xs[2][2];
    #pragma unroll
    for (int mt = 0; mt < 2; ++mt)
        #pragma unroll
        for (int b = 0; b < 2; ++b)
            xs[mt][b] = sm[XSQ_OFF + wm * 32 + mt * 16 + g + 8 * b];

    float d2acc[2][4][4];
    #pragma unroll
    for (int mt = 0; mt < 2; ++mt)
        #pragma unroll
        for (int nt = 0; nt < 4; ++nt)
            #pragma unroll
            for (int i = 0; i < 4; ++i) d2acc[mt][nt][i] = 0.f;
    float zacc[2][2] = {{0.f, 0.f}, {0.f, 0.f}};

    for (int kc = 0; kc < NCHUNK; ++kc) {
        __syncthreads();   // previous iter's B2/PF consumers done

        // ---- stage C chunk: B1 hi/lo (k=feat) and B2 hi (k=cluster) ----
        const float* cbase = cc + (size_t)kc * TKC * FDIM;
        #pragma unroll
        for (int q = 0; q < 4; ++q) {
            int cl = q * 16 + wid;                     // warp-uniform cluster
            float4 v = *(const float4*)(cbase + cl * FDIM + lane * 4);
            int nt = cl >> 3;
            int ks = lane >> 1;
            int a1base = (nt * 16 + ks) * 66 + (cl & 7) * 8 + (lane & 1);
            int a2base = (nt * 16 + ks) * 66 + (lane & 1) * 32 + (cl & 3) * 2 + ((cl & 7) >> 2);
            #pragma unroll
            for (int j = 0; j < 4; ++j) {
                float val = (&v.x)[j];
                float hi = __uint_as_float(f2tf32(val));
                float lo = val - hi;
                sm[B1H_OFF + a1base + j * 2] = hi;
                sm[B1L_OFF + a1base + j * 2] = lo;
                sm[B2H_OFF + a2base + j * 8] = hi;
            }
        }
        __syncthreads();

        // ---- GEMM1: S = x . C^T  (3xTF32: hi*hi + hi*lo + lo*hi) ----
        float sacc[2][2][4];
        #pragma unroll
        for (int mt = 0; mt < 2; ++mt)
            #pragma unroll
            for (int nt = 0; nt < 2; ++nt)
                #pragma unroll
                for (int i = 0; i < 4; ++i) sacc[mt][nt][i] = 0.f;

        #pragma unroll
        for (int ks = 0; ks < 16; ++ks) {
            uint32_t ahi[2][4], alo[2][4];
            #pragma unroll
            for (int mt = 0; mt < 2; ++mt) {
                float4 av = *(const float4*)(sm + XF_OFF +
                                ((wm * 2 + mt) * 16 + ks) * 132 + lane * 4);
                #pragma unroll
                for (int j = 0; j < 4; ++j) {
                    float xv = (&av.x)[j];
                    uint32_t h = f2tf32(xv);
                    ahi[mt][j] = h;
                    alo[mt][j] = __float_as_uint(xv - __uint_as_float(h));
                }
            }
            #pragma unroll
            for (int nt = 0; nt < 2; ++nt) {
                int ntg = wn * 2 + nt;
                float2 bh = *(const float2*)(sm + B1H_OFF + (ntg * 16 + ks) * 66 + lane * 2);
                float2 bl = *(const float2*)(sm + B1L_OFF + (ntg * 16 + ks) * 66 + lane * 2);
                #pragma unroll
                for (int mt = 0; mt < 2; ++mt) {
                    mma8(sacc[mt][nt], ahi[mt], bh);
                    mma8(sacc[mt][nt], ahi[mt], bl);
                    mma8(sacc[mt][nt], alo[mt], bh);
                }
            }
        }

        // ---- epilogue: p = exp(-sqrt(xsq+csq-2s)); Z += p; P -> PF ----
        #pragma unroll
        for (int mt = 0; mt < 2; ++mt) {
            #pragma unroll
            for (int nt = 0; nt < 2; ++nt) {
                int ksp = wn * 2 + nt;
                #pragma unroll
                for (int i = 0; i < 4; ++i) {
                    int b   = i >> 1;                 // row-high
                    int clo = 2 * tig + (i & 1);      // cluster within 8-tile
                    int clg = kc * 64 + ksp * 8 + clo;
                    float s   = sacc[mt][nt][i];
                    float d2v = fmaf(-2.f, s, xs[mt][b] + sm[CSQ_OFF + clg]);
                    float d   = sqrtf(fmaxf(d2v, 0.f));
                    float p   = __expf(-d);
                    zacc[mt][b] += p;
                    sm[PF_OFF + ((wm * 2 + mt) * 8 + ksp) * 132 +
                       (g * 4 + (clo & 3)) * 4 + b + 2 * (clo >> 2)] = p;
                }
            }
        }
        __syncthreads();

        // ---- GEMM2: D2 += P . C_chunk ----
        #pragma unroll
        for (int ks2 = 0; ks2 < 8; ++ks2) {
            uint32_t pa[2][4];
            #pragma unroll
            for (int mt = 0; mt < 2; ++mt) {
                float4 pv = *(const float4*)(sm + PF_OFF +
                                ((wm * 2 + mt) * 8 + ks2) * 132 + lane * 4);
                #pragma unroll
                for (int j = 0; j < 4; ++j) pa[mt][j] = f2tf32((&pv.x)[j]);
            }
            #pragma unroll
            for (int nt2 = 0; nt2 < 4; ++nt2) {
                int n2g = wn * 4 + nt2;
                float2 b = *(const float2*)(sm + B2H_OFF + (ks2 * 16 + n2g) * 66 + lane * 2);
                #pragma unroll
                for (int mt = 0; mt < 2; ++mt)
                    mma8(d2acc[mt][nt2], pa[mt], b);
            }
        }
    }

    // ---- Z reduction across tig lanes + the four wn warp-groups ----
    #pragma unroll
    for (int mt = 0; mt < 2; ++mt)
        #pragma unroll
        for (int b = 0; b < 2; ++b) {
            float z = zacc[mt][b];
            z += __shfl_xor_sync(0xffffffffu, z, 1);
            z += __shfl_xor_sync(0xffffffffu, z, 2);
            if (tig == 0)
                atomicAdd(&sm[ZS_OFF + wm * 32 + mt * 16 + g + 8 * b], z);
        }
    __syncthreads();

    // ---- output: out = D2 / Z ----
    float rz[2][2];
    #pragma unroll
    for (int mt = 0; mt < 2; ++mt)
        #pragma unroll
        for (int b = 0; b < 2; ++b)
            rz[mt][b] = 1.f / sm[ZS_OFF + wm * 32 + mt * 16 + g + 8 * b];

    #pragma unroll
    for (int mt = 0; mt < 2; ++mt) {
        #pragma unroll
        for (int nt2 = 0; nt2 < 4; ++nt2) {
            #pragma unroll
            for (int b = 0; b < 2; ++b) {
                size_t rowg = (size_t)blockIdx.x * TM + wm * 32 + mt * 16 + g + 8 * b;
                int f = wn * 32 + nt2 * 8 + 2 * tig;
                float2 o;
                o.x = d2acc[mt][nt2][2 * b]     * rz[mt][b];
                o.y = d2acc[mt][nt2][2 * b + 1] * rz[mt][b];
                *(float2*)(out + rowg * FDIM + f) = o;
            }
        }
    }
}

extern "C" void kernel_launch(void* const* d_in, const int* in_sizes, int n_in,
                              void* d_out, int out_size) {
    const float* x  = (const float*)d_in[0];
    const float* cc = (const float*)d_in[1];
    if (n_in >= 2 && in_sizes[0] < in_sizes[1]) {   // robustness: x is the big one
        const float* t = x; x = cc; cc = t;
    }

    cudaFuncSetAttribute(cluster_mma_kernel, cudaFuncAttributeMaxDynamicSharedMemorySize,
                         SMEM_BYTES);

    csq_kernel<<<(KCLUST + 255) / 256, 256>>>(cc);
    cluster_mma_kernel<<<MROWS / TM, THREADS, SMEM_BYTES>>>(x, cc, (float*)d_out);
}

// round 10
// speedup vs baseline: 4.2248x; 1.2361x over previous
#include <cuda_runtime.h>
#include <cstdint>
#include <math.h>

// ---------------- problem constants ----------------
#define MROWS   65536        // B*N
#define FDIM    128
#define KCLUST  512
#define TM      128          // rows per CTA
#define TKC     64           // clusters per chunk
#define NCHUNK  (KCLUST / TKC)   // 8
#define THREADS 512

// ---------------- SMEM layout (float offsets) ----------------
// XFH: X hi (tf32) in m16n8k8 A-frag order. rows = mt(8)*16+ks(16), pitch 132
// XFL: X lo packed bf16 (u16), same index space, pitch 132 u16 (= 66 u32)
// B1H: C chunk hi, GEMM1 B-frag order (n=cluster,k=feat). rows = nt*16+ks, pitch 66
// B2H: C chunk hi, GEMM2 B-frag order (n=feat,k=cluster). rows = ks2*16+nt2, pitch 66
// PF : P chunk (tf32-prerounded), GEMM2 A-frag order. rows = mt(8)*8+ks2(8), pitch 132
#define XFH_OFF  0
#define XFH_SZ   (128 * 132)
#define XFL_OFF  (XFH_OFF + XFH_SZ)          // u16 array, 128*132 u16 = 8448 floats
#define XFL_SZ   (128 * 66)
#define B1H_OFF  (XFL_OFF + XFL_SZ)
#define B1_SZ    (128 * 66)
#define B2H_OFF  (B1H_OFF + B1_SZ)
#define PF_OFF   (B2H_OFF + B1_SZ)
#define PF_SZ    (64 * 132)
#define CSQ_OFF  (PF_OFF + PF_SZ)
#define XSQ_OFF  (CSQ_OFF + 512)
#define ZS_OFF   (XSQ_OFF + 128)
#define SMEM_FLOATS (ZS_OFF + 128)
#define SMEM_BYTES  (SMEM_FLOATS * 4)

__device__ float g_csq[KCLUST];

__device__ __forceinline__ uint32_t f2tf32(float x) {
    uint32_t h; asm("cvt.rna.tf32.f32 %0, %1;" : "=r"(h) : "f"(x)); return h;
}

// D(16x8) += A(16x8,tf32) * B(8x8,tf32), fp32 accumulate
__device__ __forceinline__ void mma8(float* d, const uint32_t* a, float2 b) {
    asm volatile(
        "mma.sync.aligned.m16n8k8.row.col.f32.tf32.tf32.f32 "
        "{%0,%1,%2,%3}, {%4,%5,%6,%7}, {%8,%9}, {%0,%1,%2,%3};"
        : "+f"(d[0]), "+f"(d[1]), "+f"(d[2]), "+f"(d[3])
        : "r"(a[0]), "r"(a[1]), "r"(a[2]), "r"(a[3]),
          "r"(__float_as_uint(b.x)), "r"(__float_as_uint(b.y)));
}

__global__ void csq_kernel(const float* __restrict__ cc) {
    int c = blockIdx.x * blockDim.x + threadIdx.x;
    if (c < KCLUST) {
        const float* p = cc + (size_t)c * FDIM;
        float s = 0.f;
        #pragma unroll 16
        for (int f = 0; f < FDIM; ++f) s = fmaf(p[f], p[f], s);
        g_csq[c] = s;
    }
}

extern __shared__ float sm[];

__global__ __launch_bounds__(THREADS, 1)
void cluster_mma_kernel(const float* __restrict__ x, const float* __restrict__ cc,
                        float* __restrict__ out) {
    const int tid  = threadIdx.x;
    const int wid  = tid >> 5;      // 0..15
    const int lane = tid & 31;
    const int g    = lane >> 2;     // groupID (row within m16 tile)
    const int tig  = lane & 3;      // thread-in-group
    const int wm   = wid & 3;       // warp m-group: rows [wm*32, wm*32+32)
    const int wn   = wid >> 2;      // warp n-group: 0..3

    uint16_t* xfl = (uint16_t*)(sm + XFL_OFF);

    // ------------- prologue: split X hi/lo into A-frag order + row sumsq -------------
    const float* xbase = x + (size_t)blockIdx.x * TM * FDIM;
    #pragma unroll
    for (int q = 0; q < 8; ++q) {
        int row = q * 16 + wid;
        float4 v = *(const float4*)(xbase + row * FDIM + lane * 4);
        float s = v.x * v.x + v.y * v.y + v.z * v.z + v.w * v.w;
        #pragma unroll
        for (int m = 16; m; m >>= 1) s += __shfl_xor_sync(0xffffffffu, s, m);
        if (lane == 0) sm[XSQ_OFF + row] = s;
        int mt = row >> 4, rm = row & 15;
        int ks = lane >> 1;
        int base = (mt * 16 + ks) * 132 + (rm & 7) * 16 + (rm >> 3) + 2 * (lane & 1);
        #pragma unroll
        for (int j = 0; j < 4; ++j) {
            float xv = (&v.x)[j];
            uint32_t h = f2tf32(xv);
            float lo = xv - __uint_as_float(h);
            sm[XFH_OFF + base + j * 4] = __uint_as_float(h);
            xfl[base + j * 4] = (uint16_t)(__float_as_uint(lo) >> 16);  // bf16 truncate
        }
    }
    sm[CSQ_OFF + tid] = g_csq[tid];      // 512 threads cover all 512 entries
    if (tid < 128) sm[ZS_OFF + tid] = 0.f;
    __syncthreads();

    float xs[2][2];
    #pragma unroll
    for (int mt = 0; mt < 2; ++mt)
        #pragma unroll
        for (int b = 0; b < 2; ++b)
            xs[mt][b] = sm[XSQ_OFF + wm * 32 + mt * 16 + g + 8 * b];

    float d2acc[2][4][4];
    #pragma unroll
    for (int mt = 0; mt < 2; ++mt)
        #pragma unroll
        for (int nt = 0; nt < 4; ++nt)
            #pragma unroll
            for (int i = 0; i < 4; ++i) d2acc[mt][nt][i] = 0.f;
    float zacc[2][2] = {{0.f, 0.f}, {0.f, 0.f}};

    // prefetch chunk 0 of C into registers
    float4 pre[4];
    #pragma unroll
    for (int q = 0; q < 4; ++q) {
        int cl = q * 16 + wid;
        pre[q] = *(const float4*)(cc + (size_t)cl * FDIM + lane * 4);
    }

    for (int kc = 0; kc < NCHUNK; ++kc) {
        __syncthreads();   // previous iter's B2/PF consumers done

        // ---- stage C chunk from prefetch regs: B1H (k=feat) + B2H (k=cluster) ----
        #pragma unroll
        for (int q = 0; q < 4; ++q) {
            int cl = q * 16 + wid;                     // warp-uniform cluster
            int nt = cl >> 3;
            int ks = lane >> 1;
            int a1base = (nt * 16 + ks) * 66 + (cl & 7) * 8 + (lane & 1);
            int a2base = (nt * 16 + ks) * 66 + (lane & 1) * 32 + (cl & 3) * 2 + ((cl & 7) >> 2);
            #pragma unroll
            for (int j = 0; j < 4; ++j) {
                float hi = __uint_as_float(f2tf32((&pre[q].x)[j]));
                sm[B1H_OFF + a1base + j * 2] = hi;
                sm[B2H_OFF + a2base + j * 8] = hi;
            }
        }
        __syncthreads();

        // prefetch next chunk (latency hidden behind GEMM1 + epilogue)
        if (kc + 1 < NCHUNK) {
            #pragma unroll
            for (int q = 0; q < 4; ++q) {
                int cl = (kc + 1) * TKC + q * 16 + wid;
                pre[q] = *(const float4*)(cc + (size_t)cl * FDIM + lane * 4);
            }
        }

        // ---- GEMM1: S = x . C_hi^T  (2-term: xhi*ch + xlo*ch) ----
        float sacc[2][2][4];
        #pragma unroll
        for (int mt = 0; mt < 2; ++mt)
            #pragma unroll
            for (int nt = 0; nt < 2; ++nt)
                #pragma unroll
                for (int i = 0; i < 4; ++i) sacc[mt][nt][i] = 0.f;

        #pragma unroll
        for (int ks = 0; ks < 16; ++ks) {
            uint32_t ahi[2][4], alo[2][4];
            #pragma unroll
            for (int mt = 0; mt < 2; ++mt) {
                int arow = (wm * 2 + mt) * 16 + ks;
                float4 av = *(const float4*)(sm + XFH_OFF + arow * 132 + lane * 4);
                uint2 lv = *(const uint2*)((const uint32_t*)xfl + arow * 66 + lane * 2);
                ahi[mt][0] = __float_as_uint(av.x);
                ahi[mt][1] = __float_as_uint(av.y);
                ahi[mt][2] = __float_as_uint(av.z);
                ahi[mt][3] = __float_as_uint(av.w);
                alo[mt][0] = lv.x << 16;
                alo[mt][1] = lv.x & 0xFFFF0000u;
                alo[mt][2] = lv.y << 16;
                alo[mt][3] = lv.y & 0xFFFF0000u;
            }
            #pragma unroll
            for (int nt = 0; nt < 2; ++nt) {
                int ntg = wn * 2 + nt;
                float2 bh = *(const float2*)(sm + B1H_OFF + (ntg * 16 + ks) * 66 + lane * 2);
                #pragma unroll
                for (int mt = 0; mt < 2; ++mt) {
                    mma8(sacc[mt][nt], ahi[mt], bh);
                    mma8(sacc[mt][nt], alo[mt], bh);
                }
            }
        }

        // ---- epilogue: p = exp(-sqrt(xsq+csq-2s)); Z += p; tf32(p) -> PF ----
        #pragma unroll
        for (int mt = 0; mt < 2; ++mt) {
            #pragma unroll
            for (int nt = 0; nt < 2; ++nt) {
                int ksp = wn * 2 + nt;
                #pragma unroll
                for (int i = 0; i < 4; ++i) {
                    int b   = i >> 1;                 // row-high
                    int clo = 2 * tig + (i & 1);      // cluster within 8-tile
                    int clg = kc * 64 + ksp * 8 + clo;
                    float s   = sacc[mt][nt][i];
                    float d2v = fmaf(-2.f, s, xs[mt][b] + sm[CSQ_OFF + clg]);
                    float d   = sqrtf(fmaxf(d2v, 0.f));
                    float p   = __expf(-d);
                    zacc[mt][b] += p;
                    sm[PF_OFF + ((wm * 2 + mt) * 8 + ksp) * 132 +
                       (g * 4 + (clo & 3)) * 4 + b + 2 * (clo >> 2)] =
                        __uint_as_float(f2tf32(p));
                }
            }
        }
        __syncthreads();

        // ---- GEMM2: D2 += P . C_chunk  (A already tf32, no cvt) ----
        #pragma unroll
        for (int ks2 = 0; ks2 < 8; ++ks2) {
            uint32_t pa[2][4];
            #pragma unroll
            for (int mt = 0; mt < 2; ++mt) {
                float4 pv = *(const float4*)(sm + PF_OFF +
                                ((wm * 2 + mt) * 8 + ks2) * 132 + lane * 4);
                pa[mt][0] = __float_as_uint(pv.x);
                pa[mt][1] = __float_as_uint(pv.y);
                pa[mt][2] = __float_as_uint(pv.z);
                pa[mt][3] = __float_as_uint(pv.w);
            }
            #pragma unroll
            for (int nt2 = 0; nt2 < 4; ++nt2) {
                int n2g = wn * 4 + nt2;
                float2 b = *(const float2*)(sm + B2H_OFF + (ks2 * 16 + n2g) * 66 + lane * 2);
                #pragma unroll
                for (int mt = 0; mt < 2; ++mt)
                    mma8(d2acc[mt][nt2], pa[mt], b);
            }
        }
    }

    // ---- Z reduction across tig lanes + the four wn warp-groups ----
    #pragma unroll
    for (int mt = 0; mt < 2; ++mt)
        #pragma unroll
        for (int b = 0; b < 2; ++b) {
            float z = zacc[mt][b];
            z += __shfl_xor_sync(0xffffffffu, z, 1);
            z += __shfl_xor_sync(0xffffffffu, z, 2);
            if (tig == 0)
                atomicAdd(&sm[ZS_OFF + wm * 32 + mt * 16 + g + 8 * b], z);
        }
    __syncthreads();

    // ---- output: out = D2 / Z ----
    float rz[2][2];
    #pragma unroll
    for (int mt = 0; mt < 2; ++mt)
        #pragma unroll
        for (int b = 0; b < 2; ++b)
            rz[mt][b] = 1.f / sm[ZS_OFF + wm * 32 + mt * 16 + g + 8 * b];

    #pragma unroll
    for (int mt = 0; mt < 2; ++mt) {
        #pragma unroll
        for (int nt2 = 0; nt2 < 4; ++nt2) {
            #pragma unroll
            for (int b = 0; b < 2; ++b) {
                size_t rowg = (size_t)blockIdx.x * TM + wm * 32 + mt * 16 + g + 8 * b;
                int f = wn * 32 + nt2 * 8 + 2 * tig;
                float2 o;
                o.x = d2acc[mt][nt2][2 * b]     * rz[mt][b];
                o.y = d2acc[mt][nt2][2 * b + 1] * rz[mt][b];
                *(float2*)(out + rowg * FDIM + f) = o;
            }
        }
    }
}

extern "C" void kernel_launch(void* const* d_in, const int* in_sizes, int n_in,
                              void* d_out, int out_size) {
    const float* x  = (const float*)d_in[0];
    const float* cc = (const float*)d_in[1];
    if (n_in >= 2 && in_sizes[0] < in_sizes[1]) {   // robustness: x is the big one
        const float* t = x; x = cc; cc = t;
    }

    cudaFuncSetAttribute(cluster_mma_kernel, cudaFuncAttributeMaxDynamicSharedMemorySize,
                         SMEM_BYTES);

    csq_kernel<<<(KCLUST + 255) / 256, 256>>>(cc);
    cluster_mma_kernel<<<MROWS / TM, THREADS, SMEM_BYTES>>>(x, cc, (float*)d_out);
}

// round 11
// speedup vs baseline: 4.3997x; 1.0414x over previous
#include <cuda_runtime.h>
#include <cstdint>
#include <math.h>

// ---------------- problem constants ----------------
#define MROWS   65536        // B*N
#define FDIM    128
#define KCLUST  512
#define TM      64           // rows per CTA
#define TKC     32           // clusters per chunk
#define NCHUNK  (KCLUST / TKC)   // 16
#define THREADS 256

// ---------------- SMEM layout (float offsets) ----------------
// XFH: X hi (tf32) in m16n8k8 A-frag order. rows = mt(4)*16+ks(16), pitch 132
// XFL: X lo packed bf16 (u16), same index space, pitch 132 u16 (= 66 u32)
// B1H: C chunk hi, GEMM1 B-frag order (n=cluster,k=feat). rows = nt(4)*16+ks(16), pitch 66
// B2H: C chunk hi, GEMM2 B-frag order (n=feat,k=cluster). rows = ks2(4)*16+nt2(16), pitch 66
// PF : P chunk (tf32-prerounded), GEMM2 A-frag order. rows = mtile(4)*4+ksp(4), pitch 132
#define XFH_OFF  0
#define XFH_SZ   (64 * 132)
#define XFL_OFF  (XFH_OFF + XFH_SZ)          // u16 array, 64*132 u16 = 4224 floats
#define XFL_SZ   (64 * 66)
#define B1H_OFF  (XFL_OFF + XFL_SZ)
#define B1_SZ    (64 * 66)
#define B2H_OFF  (B1H_OFF + B1_SZ)
#define B2_SZ    (64 * 66)
#define PF_OFF   (B2H_OFF + B2_SZ)
#define PF_SZ    (16 * 132)
#define CSQ_OFF  (PF_OFF + PF_SZ)
#define XSQ_OFF  (CSQ_OFF + 512)
#define ZS_OFF   (XSQ_OFF + 64)
#define SMEM_FLOATS (ZS_OFF + 64)
#define SMEM_BYTES  (SMEM_FLOATS * 4)

__device__ float g_csq[KCLUST];

__device__ __forceinline__ uint32_t f2tf32(float x) {
    uint32_t h; asm("cvt.rna.tf32.f32 %0, %1;" : "=r"(h) : "f"(x)); return h;
}

// D(16x8) += A(16x8,tf32) * B(8x8,tf32), fp32 accumulate
__device__ __forceinline__ void mma8(float* d, const uint32_t* a, float2 b) {
    asm volatile(
        "mma.sync.aligned.m16n8k8.row.col.f32.tf32.tf32.f32 "
        "{%0,%1,%2,%3}, {%4,%5,%6,%7}, {%8,%9}, {%0,%1,%2,%3};"
        : "+f"(d[0]), "+f"(d[1]), "+f"(d[2]), "+f"(d[3])
        : "r"(a[0]), "r"(a[1]), "r"(a[2]), "r"(a[3]),
          "r"(__float_as_uint(b.x)), "r"(__float_as_uint(b.y)));
}

__global__ void csq_kernel(const float* __restrict__ cc) {
    int c = blockIdx.x * blockDim.x + threadIdx.x;
    if (c < KCLUST) {
        const float* p = cc + (size_t)c * FDIM;
        float s = 0.f;
        #pragma unroll 16
        for (int f = 0; f < FDIM; ++f) s = fmaf(p[f], p[f], s);
        g_csq[c] = s;
    }
}

extern __shared__ float sm[];

__global__ __launch_bounds__(THREADS, 2)
void cluster_mma_kernel(const float* __restrict__ x, const float* __restrict__ cc,
                        float* __restrict__ out) {
    const int tid  = threadIdx.x;
    const int wid  = tid >> 5;      // 0..7
    const int lane = tid & 31;
    const int g    = lane >> 2;     // groupID (row within m16 tile)
    const int tig  = lane & 3;      // thread-in-group
    const int wm   = wid & 3;       // warp m-group: owns m-tile wm (rows wm*16..+16)
    const int wn   = wid >> 2;      // warp n-group: 0..1

    uint16_t* xfl = (uint16_t*)(sm + XFL_OFF);

    // ------------- prologue: split X hi/lo into A-frag order + row sumsq -------------
    const float* xbase = x + (size_t)blockIdx.x * TM * FDIM;
    #pragma unroll
    for (int q = 0; q < 8; ++q) {
        int row = q * 8 + wid;                 // 0..63
        float4 v = *(const float4*)(xbase + row * FDIM + lane * 4);
        float s = v.x * v.x + v.y * v.y + v.z * v.z + v.w * v.w;
        #pragma unroll
        for (int m = 16; m; m >>= 1) s += __shfl_xor_sync(0xffffffffu, s, m);
        if (lane == 0) sm[XSQ_OFF + row] = s;
        int mt = row >> 4, rm = row & 15;
        int ks = lane >> 1;
        int base = (mt * 16 + ks) * 132 + (rm & 7) * 16 + (rm >> 3) + 2 * (lane & 1);
        #pragma unroll
        for (int j = 0; j < 4; ++j) {
            float xv = (&v.x)[j];
            uint32_t h = f2tf32(xv);
            float lo = xv - __uint_as_float(h);
            sm[XFH_OFF + base + j * 4] = __uint_as_float(h);
            xfl[base + j * 4] = (uint16_t)(__float_as_uint(lo) >> 16);  // bf16 truncate
        }
    }
    sm[CSQ_OFF + tid]       = g_csq[tid];
    sm[CSQ_OFF + 256 + tid] = g_csq[256 + tid];
    if (tid < 64) sm[ZS_OFF + tid] = 0.f;
    __syncthreads();

    float xs[2];
    #pragma unroll
    for (int b = 0; b < 2; ++b)
        xs[b] = sm[XSQ_OFF + wm * 16 + g + 8 * b];

    float d2acc[8][4];
    #pragma unroll
    for (int nt = 0; nt < 8; ++nt)
        #pragma unroll
        for (int i = 0; i < 4; ++i) d2acc[nt][i] = 0.f;
    float zacc[2] = {0.f, 0.f};

    // prefetch chunk 0 of C into registers (32 clusters x 128 feats)
    float4 pre[4];
    #pragma unroll
    for (int q = 0; q < 4; ++q) {
        int cl = q * 8 + wid;
        pre[q] = *(const float4*)(cc + (size_t)cl * FDIM + lane * 4);
    }

    for (int kc = 0; kc < NCHUNK; ++kc) {
        __syncthreads();   // previous iter's B2/PF consumers done

        // ---- stage C chunk from prefetch regs: B1H (k=feat) + B2H (k=cluster) ----
        #pragma unroll
        for (int q = 0; q < 4; ++q) {
            int cl = q * 8 + wid;                      // warp-uniform cluster 0..31
            int nt = cl >> 3;                          // 0..3
            int ks = lane >> 1;
            int a1base = (nt * 16 + ks) * 66 + (cl & 7) * 8 + (lane & 1);
            int a2base = (nt * 16 + ks) * 66 + (lane & 1) * 32 + (cl & 3) * 2 + ((cl & 7) >> 2);
            #pragma unroll
            for (int j = 0; j < 4; ++j) {
                float hi = __uint_as_float(f2tf32((&pre[q].x)[j]));
                sm[B1H_OFF + a1base + j * 2] = hi;
                sm[B2H_OFF + a2base + j * 8] = hi;
            }
        }
        __syncthreads();

        // prefetch next chunk (latency hidden behind GEMM1 + epilogue)
        if (kc + 1 < NCHUNK) {
            #pragma unroll
            for (int q = 0; q < 4; ++q) {
                int cl = (kc + 1) * TKC + q * 8 + wid;
                pre[q] = *(const float4*)(cc + (size_t)cl * FDIM + lane * 4);
            }
        }

        // ---- GEMM1: S = x . C_hi^T  (2-term: xhi*ch + xlo*ch) ----
        float sacc[2][4];
        #pragma unroll
        for (int nt = 0; nt < 2; ++nt)
            #pragma unroll
            for (int i = 0; i < 4; ++i) sacc[nt][i] = 0.f;

        #pragma unroll
        for (int ks = 0; ks < 16; ++ks) {
            uint32_t ahi[4], alo[4];
            int arow = wm * 16 + ks;
            float4 av = *(const float4*)(sm + XFH_OFF + arow * 132 + lane * 4);
            uint2 lv = *(const uint2*)((const uint32_t*)xfl + arow * 66 + lane * 2);
            ahi[0] = __float_as_uint(av.x);
            ahi[1] = __float_as_uint(av.y);
            ahi[2] = __float_as_uint(av.z);
            ahi[3] = __float_as_uint(av.w);
            alo[0] = lv.x << 16;
            alo[1] = lv.x & 0xFFFF0000u;
            alo[2] = lv.y << 16;
            alo[3] = lv.y & 0xFFFF0000u;
            #pragma unroll
            for (int nt = 0; nt < 2; ++nt) {
                int ntg = wn * 2 + nt;
                float2 bh = *(const float2*)(sm + B1H_OFF + (ntg * 16 + ks) * 66 + lane * 2);
                mma8(sacc[nt], ahi, bh);
                mma8(sacc[nt], alo, bh);
            }
        }

        // ---- epilogue: p = exp(-sqrt(xsq+csq-2s)); Z += p; tf32(p) -> PF ----
        #pragma unroll
        for (int nt = 0; nt < 2; ++nt) {
            int ksp = wn * 2 + nt;
            #pragma unroll
            for (int i = 0; i < 4; ++i) {
                int b   = i >> 1;                 // row-high
                int clo = 2 * tig + (i & 1);      // cluster within 8-tile
                int clg = kc * TKC + ksp * 8 + clo;
                float s   = sacc[nt][i];
                float d2v = fmaf(-2.f, s, xs[b] + sm[CSQ_OFF + clg]);
                float d   = sqrtf(fmaxf(d2v, 0.f));
                float p   = __expf(-d);
                zacc[b] += p;
                sm[PF_OFF + (wm * 4 + ksp) * 132 +
                   (g * 4 + (clo & 3)) * 4 + b + 2 * (clo >> 2)] =
                    __uint_as_float(f2tf32(p));
            }
        }
        __syncthreads();

        // ---- GEMM2: D2 += P . C_chunk  (A already tf32, no cvt) ----
        #pragma unroll
        for (int ks2 = 0; ks2 < 4; ++ks2) {
            uint32_t pa[4];
            float4 pv = *(const float4*)(sm + PF_OFF + (wm * 4 + ks2) * 132 + lane * 4);
            pa[0] = __float_as_uint(pv.x);
            pa[1] = __float_as_uint(pv.y);
            pa[2] = __float_as_uint(pv.z);
            pa[3] = __float_as_uint(pv.w);
            #pragma unroll
            for (int nt2 = 0; nt2 < 8; ++nt2) {
                int n2g = wn * 8 + nt2;
                float2 b = *(const float2*)(sm + B2H_OFF + (ks2 * 16 + n2g) * 66 + lane * 2);
                mma8(d2acc[nt2], pa, b);
            }
        }
    }

    // ---- Z reduction across tig lanes + the two wn warp-groups ----
    #pragma unroll
    for (int b = 0; b < 2; ++b) {
        float z = zacc[b];
        z += __shfl_xor_sync(0xffffffffu, z, 1);
        z += __shfl_xor_sync(0xffffffffu, z, 2);
        if (tig == 0)
            atomicAdd(&sm[ZS_OFF + wm * 16 + g + 8 * b], z);
    }
    __syncthreads();

    // ---- output: out = D2 / Z ----
    float rz[2];
    #pragma unroll
    for (int b = 0; b < 2; ++b)
        rz[b] = 1.f / sm[ZS_OFF + wm * 16 + g + 8 * b];

    #pragma unroll
    for (int nt2 = 0; nt2 < 8; ++nt2) {
        #pragma unroll
        for (int b = 0; b < 2; ++b) {
            size_t rowg = (size_t)blockIdx.x * TM + wm * 16 + g + 8 * b;
            int f = wn * 64 + nt2 * 8 + 2 * tig;
            float2 o;
            o.x = d2acc[nt2][2 * b]     * rz[b];
            o.y = d2acc[nt2][2 * b + 1] * rz[b];
            *(float2*)(out + rowg * FDIM + f) = o;
        }
    }
}

extern "C" void kernel_launch(void* const* d_in, const int* in_sizes, int n_in,
                              void* d_out, int out_size) {
    const float* x  = (const float*)d_in[0];
    const float* cc = (const float*)d_in[1];
    if (n_in >= 2 && in_sizes[0] < in_sizes[1]) {   // robustness: x is the big one
        const float* t = x; x = cc; cc = t;
    }

    cudaFuncSetAttribute(cluster_mma_kernel, cudaFuncAttributeMaxDynamicSharedMemorySize,
                         SMEM_BYTES);

    csq_kernel<<<(KCLUST + 255) / 256, 256>>>(cc);
    cluster_mma_kernel<<<MROWS / TM, THREADS, SMEM_BYTES>>>(x, cc, (float*)d_out);
}

// round 12
// speedup vs baseline: 4.4124x; 1.0029x over previous
#include <cuda_runtime.h>
#include <cstdint>
#include <math.h>

// ---------------- problem constants ----------------
#define MROWS   65536        // B*N
#define FDIM    128
#define KCLUST  512
#define TM      64           // rows per CTA
#define TKC     32           // clusters per chunk
#define NCHUNK  (KCLUST / TKC)   // 16
#define THREADS 256

// ---------------- SMEM layout (float offsets) ----------------
// XFH: X hi (tf32) in m16n8k8 A-frag order. rows = mt(4)*16+ks(16), pitch 132
// XFL: X lo packed bf16 (u16), same index space, pitch 132 u16 (= 66 u32)
// B1H: C chunk hi, GEMM1 B-frag order (n=cluster,k=feat). rows = nt(4)*16+ks(16), pitch 66
// B2H: C chunk hi, GEMM2 B-frag order (n=feat,k=cluster). rows = ks2(4)*16+nt2(16), pitch 66
// PF : P chunk (tf32-prerounded), GEMM2 A-frag order. rows = mtile(4)*4+ksp(4), pitch 132
#define XFH_OFF  0
#define XFH_SZ   (64 * 132)
#define XFL_OFF  (XFH_OFF + XFH_SZ)          // u16 array, 64*132 u16 = 4224 floats
#define XFL_SZ   (64 * 66)
#define B1H_OFF  (XFL_OFF + XFL_SZ)
#define B1_SZ    (64 * 66)
#define B2H_OFF  (B1H_OFF + B1_SZ)
#define B2_SZ    (64 * 66)
#define PF_OFF   (B2H_OFF + B2_SZ)
#define PF_SZ    (16 * 132)
#define CSQ_OFF  (PF_OFF + PF_SZ)
#define XSQ_OFF  (CSQ_OFF + 512)
#define ZS_OFF   (XSQ_OFF + 64)
#define SMEM_FLOATS (ZS_OFF + 64)
#define SMEM_BYTES  (SMEM_FLOATS * 4)

__device__ float g_csq[KCLUST];

__device__ __forceinline__ uint32_t f2tf32(float x) {
    uint32_t h; asm("cvt.rna.tf32.f32 %0, %1;" : "=r"(h) : "f"(x)); return h;
}

// D(16x8) += A(16x8,tf32) * B(8x8,tf32), fp32 accumulate
__device__ __forceinline__ void mma8(float* d, const uint32_t* a, float2 b) {
    asm volatile(
        "mma.sync.aligned.m16n8k8.row.col.f32.tf32.tf32.f32 "
        "{%0,%1,%2,%3}, {%4,%5,%6,%7}, {%8,%9}, {%0,%1,%2,%3};"
        : "+f"(d[0]), "+f"(d[1]), "+f"(d[2]), "+f"(d[3])
        : "r"(a[0]), "r"(a[1]), "r"(a[2]), "r"(a[3]),
          "r"(__float_as_uint(b.x)), "r"(__float_as_uint(b.y)));
}

__global__ void csq_kernel(const float* __restrict__ cc) {
    int c = blockIdx.x * blockDim.x + threadIdx.x;
    if (c < KCLUST) {
        const float* p = cc + (size_t)c * FDIM;
        float s = 0.f;
        #pragma unroll 16
        for (int f = 0; f < FDIM; ++f) s = fmaf(p[f], p[f], s);
        g_csq[c] = s;
    }
}

extern __shared__ float sm[];

__global__ __launch_bounds__(THREADS, 2)
void cluster_mma_kernel(const float* __restrict__ x, const float* __restrict__ cc,
                        float* __restrict__ out) {
    const int tid  = threadIdx.x;
    const int wid  = tid >> 5;      // 0..7
    const int lane = tid & 31;
    const int g    = lane >> 2;     // groupID (row within m16 tile)
    const int tig  = lane & 3;      // thread-in-group
    const int wm   = wid & 3;       // warp m-group: owns m-tile wm (rows wm*16..+16)
    const int wn   = wid >> 2;      // warp n-group: 0..1

    uint16_t* xfl = (uint16_t*)(sm + XFL_OFF);

    // ------------- prologue: split X hi/lo into A-frag order + row sumsq -------------
    const float* xbase = x + (size_t)blockIdx.x * TM * FDIM;
    #pragma unroll
    for (int q = 0; q < 8; ++q) {
        int row = q * 8 + wid;                 // 0..63
        float4 v = *(const float4*)(xbase + row * FDIM + lane * 4);
        float s = v.x * v.x + v.y * v.y + v.z * v.z + v.w * v.w;
        #pragma unroll
        for (int m = 16; m; m >>= 1) s += __shfl_xor_sync(0xffffffffu, s, m);
        if (lane == 0) sm[XSQ_OFF + row] = s;
        int mt = row >> 4, rm = row & 15;
        int ks = lane >> 1;
        int base = (mt * 16 + ks) * 132 + (rm & 7) * 16 + (rm >> 3) + 2 * (lane & 1);
        #pragma unroll
        for (int j = 0; j < 4; ++j) {
            float xv = (&v.x)[j];
            uint32_t h = f2tf32(xv);
            float lo = xv - __uint_as_float(h);
            sm[XFH_OFF + base + j * 4] = __uint_as_float(h);
            xfl[base + j * 4] = (uint16_t)(__float_as_uint(lo) >> 16);  // bf16 truncate
        }
    }
    sm[CSQ_OFF + tid]       = g_csq[tid];
    sm[CSQ_OFF + 256 + tid] = g_csq[256 + tid];
    if (tid < 64) sm[ZS_OFF + tid] = 0.f;
    __syncthreads();

    float xs[2];
    #pragma unroll
    for (int b = 0; b < 2; ++b)
        xs[b] = sm[XSQ_OFF + wm * 16 + g + 8 * b];

    float d2acc[8][4];
    #pragma unroll
    for (int nt = 0; nt < 8; ++nt)
        #pragma unroll
        for (int i = 0; i < 4; ++i) d2acc[nt][i] = 0.f;
    float zacc[2] = {0.f, 0.f};

    // prefetch chunk 0 of C into registers (32 clusters x 128 feats)
    float4 pre[4];
    #pragma unroll
    for (int q = 0; q < 4; ++q) {
        int cl = q * 8 + wid;
        pre[q] = *(const float4*)(cc + (size_t)cl * FDIM + lane * 4);
    }

    for (int kc = 0; kc < NCHUNK; ++kc) {
        __syncthreads();   // previous iter's B2/PF consumers done

        // ---- stage C chunk from prefetch regs: B1H (k=feat) + B2H (k=cluster) ----
        #pragma unroll
        for (int q = 0; q < 4; ++q) {
            int cl = q * 8 + wid;                      // warp-uniform cluster 0..31
            int nt = cl >> 3;                          // 0..3
            int ks = lane >> 1;
            int a1base = (nt * 16 + ks) * 66 + (cl & 7) * 8 + (lane & 1);
            int a2base = (nt * 16 + ks) * 66 + (lane & 1) * 32 + (cl & 3) * 2 + ((cl & 7) >> 2);
            #pragma unroll
            for (int j = 0; j < 4; ++j) {
                float hi = __uint_as_float(f2tf32((&pre[q].x)[j]));
                sm[B1H_OFF + a1base + j * 2] = hi;
                sm[B2H_OFF + a2base + j * 8] = hi;
            }
        }
        __syncthreads();

        // prefetch next chunk (latency hidden behind GEMM1 + epilogue)
        if (kc + 1 < NCHUNK) {
            #pragma unroll
            for (int q = 0; q < 4; ++q) {
                int cl = (kc + 1) * TKC + q * 8 + wid;
                pre[q] = *(const float4*)(cc + (size_t)cl * FDIM + lane * 4);
            }
        }

        // ---- GEMM1: S = x . C_hi^T  (2-term: xhi*ch + xlo*ch) ----
        float sacc[2][4];
        #pragma unroll
        for (int nt = 0; nt < 2; ++nt)
            #pragma unroll
            for (int i = 0; i < 4; ++i) sacc[nt][i] = 0.f;

        #pragma unroll
        for (int ks = 0; ks < 16; ++ks) {
            uint32_t ahi[4], alo[4];
            int arow = wm * 16 + ks;
            float4 av = *(const float4*)(sm + XFH_OFF + arow * 132 + lane * 4);
            uint2 lv = *(const uint2*)((const uint32_t*)xfl + arow * 66 + lane * 2);
            ahi[0] = __float_as_uint(av.x);
            ahi[1] = __float_as_uint(av.y);
            ahi[2] = __float_as_uint(av.z);
            ahi[3] = __float_as_uint(av.w);
            alo[0] = lv.x << 16;
            alo[1] = lv.x & 0xFFFF0000u;
            alo[2] = lv.y << 16;
            alo[3] = lv.y & 0xFFFF0000u;
            #pragma unroll
            for (int nt = 0; nt < 2; ++nt) {
                int ntg = wn * 2 + nt;
                float2 bh = *(const float2*)(sm + B1H_OFF + (ntg * 16 + ks) * 66 + lane * 2);
                mma8(sacc[nt], ahi, bh);
                mma8(sacc[nt], alo, bh);
            }
        }

        // ---- epilogue: p = exp(-sqrt(xsq+csq-2s)); Z += p; tf32(p) -> PF ----
        #pragma unroll
        for (int nt = 0; nt < 2; ++nt) {
            int ksp = wn * 2 + nt;
            #pragma unroll
            for (int i = 0; i < 4; ++i) {
                int b   = i >> 1;                 // row-high
                int clo = 2 * tig + (i & 1);      // cluster within 8-tile
                int clg = kc * TKC + ksp * 8 + clo;
                float s   = sacc[nt][i];
                float d2v = fmaf(-2.f, s, xs[b] + sm[CSQ_OFF + clg]);
                float d   = sqrtf(fmaxf(d2v, 0.f));
                float p   = __expf(-d);
                zacc[b] += p;
                sm[PF_OFF + (wm * 4 + ksp) * 132 +
                   (g * 4 + (clo & 3)) * 4 + b + 2 * (clo >> 2)] =
                    __uint_as_float(f2tf32(p));
            }
        }
        __syncthreads();

        // ---- GEMM2: D2 += P . C_chunk  (A already tf32, no cvt) ----
        #pragma unroll
        for (int ks2 = 0; ks2 < 4; ++ks2) {
            uint32_t pa[4];
            float4 pv = *(const float4*)(sm + PF_OFF + (wm * 4 + ks2) * 132 + lane * 4);
            pa[0] = __float_as_uint(pv.x);
            pa[1] = __float_as_uint(pv.y);
            pa[2] = __float_as_uint(pv.z);
            pa[3] = __float_as_uint(pv.w);
            #pragma unroll
            for (int nt2 = 0; nt2 < 8; ++nt2) {
                int n2g = wn * 8 + nt2;
                float2 b = *(const float2*)(sm + B2H_OFF + (ks2 * 16 + n2g) * 66 + lane * 2);
                mma8(d2acc[nt2], pa, b);
            }
        }
    }

    // ---- Z reduction across tig lanes + the two wn warp-groups ----
    #pragma unroll
    for (int b = 0; b < 2; ++b) {
        float z = zacc[b];
        z += __shfl_xor_sync(0xffffffffu, z, 1);
        z += __shfl_xor_sync(0xffffffffu, z, 2);
        if (tig == 0)
            atomicAdd(&sm[ZS_OFF + wm * 16 + g + 8 * b], z);
    }
    __syncthreads();

    // ---- output: out = D2 / Z ----
    float rz[2];
    #pragma unroll
    for (int b = 0; b < 2; ++b)
        rz[b] = 1.f / sm[ZS_OFF + wm * 16 + g + 8 * b];

    #pragma unroll
    for (int nt2 = 0; nt2 < 8; ++nt2) {
        #pragma unroll
        for (int b = 0; b < 2; ++b) {
            size_t rowg = (size_t)blockIdx.x * TM + wm * 16 + g + 8 * b;
            int f = wn * 64 + nt2 * 8 + 2 * tig;
            float2 o;
            o.x = d2acc[nt2][2 * b]     * rz[b];
            o.y = d2acc[nt2][2 * b + 1] * rz[b];
            *(float2*)(out + rowg * FDIM + f) = o;
        }
    }
}

extern "C" void kernel_launch(void* const* d_in, const int* in_sizes, int n_in,
                              void* d_out, int out_size) {
    const float* x  = (const float*)d_in[0];
    const float* cc = (const float*)d_in[1];
    if (n_in >= 2 && in_sizes[0] < in_sizes[1]) {   // robustness: x is the big one
        const float* t = x; x = cc; cc = t;
    }

    cudaFuncSetAttribute(cluster_mma_kernel, cudaFuncAttributeMaxDynamicSharedMemorySize,
                         SMEM_BYTES);

    csq_kernel<<<(KCLUST + 255) / 256, 256>>>(cc);
    cluster_mma_kernel<<<MROWS / TM, THREADS, SMEM_BYTES>>>(x, cc, (float*)d_out);
}